// round 17
// baseline (speedup 1.0000x reference)
#include <cuda_runtime.h>

// Levinson-Durbin, one thread per batch (B=65536, M=64).
// R15 = R14 resubmitted unchanged (R14 bench was an infra failure, the
// kernel never ran). R7 byte-identical body (25.06us best: shared-r,
// 4-acc dot, negInvE off-critical-path division) with ONLY the occupancy
// bound raised: __launch_bounds__(64, 9) -> 113-reg budget -> 9 CTAs/SM
// = 18 warps/SM = 4.5 warps/SMSP (vs R7's 3.5).
// Rationale: measured issue=47% at 3.5 warps/SMSP with ~23.8K issue-cycles
// of per-SMSP demand -> eligibility-bound, not pipe-bound; more resident
// warps is the only remaining lever on this proven instruction stream.
// True register state = a[64] + ~40 temps, well under 113 -> no spills
// expected (unlike R2-R4 caps, which sat below the then-129-float state).

constexpr int M  = 64;
constexpr int NR = M + 1;   // 65 floats per row
constexpr int BT = 64;      // threads (= batches) per block

__global__ __launch_bounds__(BT, 9)
void levdur_kernel(const float* __restrict__ g_r,
                   float* __restrict__ g_out)
{
    __shared__ float sm[BT * NR];   // 16,640 B; 9 CTAs -> 150 KB of 228 KB
    const int tid = threadIdx.x;
    const long long base = (long long)blockIdx.x * BT * NR;

    // Coalesced load: flat copy of this block's 64 rows (exact fit, no guards).
    #pragma unroll
    for (int i = 0; i < NR; ++i) {
        sm[i * BT + tid] = g_r[base + (long long)i * BT + tid];
    }
    __syncthreads();

    float* r = &sm[tid * NR];   // private row; stride 65 -> conflict-free

    {
        float a[NR];            // a[1..M] in registers (constant indices)
        const float r0 = r[0];
        float negInvE = __fdividef(-1.0f, r0);   // -1/E_0
        float P = 1.0f;                          // prod of (1 - k^2)

        #pragma unroll
        for (int m = 1; m <= M; ++m) {
            // num = r[m] + sum_{j=1}^{m-1} a[j] * r[m-j], 4-way ILP split.
            float acc0 = r[m], acc1 = 0.0f, acc2 = 0.0f, acc3 = 0.0f;
            #pragma unroll
            for (int j = 1; j <= m - 1; ++j) {
                switch ((j - 1) & 3) {
                    case 0: acc0 = fmaf(a[j], r[m - j], acc0); break;
                    case 1: acc1 = fmaf(a[j], r[m - j], acc1); break;
                    case 2: acc2 = fmaf(a[j], r[m - j], acc2); break;
                    default: acc3 = fmaf(a[j], r[m - j], acc3); break;
                }
            }
            float num = (acc0 + acc1) + (acc2 + acc3);

            float k = num * negInvE;             // = -num / E   (4-cyc path)

            // Off-critical-path refresh for next step (hidden under update+dot):
            float c = fmaf(-k, k, 1.0f);         // 1 - k^2
            P *= c;
            negInvE = __fdividef(negInvE, c);    // RCP overlaps with below

            // a_new[j] = a[j] + k * a[m-j], symmetric pairs in place.
            #pragma unroll
            for (int i = 1; i < m - i; ++i) {
                float t = a[i];
                a[i]     = fmaf(k, a[m - i], t);
                a[m - i] = fmaf(k, t, a[m - i]);
            }
            if ((m & 1) == 0 && m >= 2) {        // middle element (m even)
                int h = m >> 1;
                a[h] = fmaf(k, a[h], a[h]);
            }
            a[m] = k;
        }

        // Result into our shared row: [K, a1..aM],  K = sqrt(r0 * prod c).
        r[0] = sqrtf(r0 * P);
        #pragma unroll
        for (int i = 1; i <= M; ++i) r[i] = a[i];
    }
    __syncthreads();

    // Coalesced store (exact fit, no guards).
    #pragma unroll
    for (int i = 0; i < NR; ++i) {
        g_out[base + (long long)i * BT + tid] = sm[i * BT + tid];
    }
}

extern "C" void kernel_launch(void* const* d_in, const int* in_sizes, int n_in,
                              void* d_out, int out_size)
{
    const float* r = (const float*)d_in[0];
    float* out = (float*)d_out;
    int nbatch = in_sizes[0] / NR;           // 65536 (exact multiple of BT)
    int grid = nbatch / BT;                  // 1024
    levdur_kernel<<<grid, BT>>>(r, out);
}